// round 8
// baseline (speedup 1.0000x reference)
#include <cuda_runtime.h>

// Problem: B=8, H=512, W=512
// Inputs: t(8,1,1,1) I0,I1(8,512,512,3) interp(8,512,512,5) Fhat_t0/t1(8,512,512,2)
// Output: It (8,512,512,3) float32

#define W_DIM 512
#define H_DIM 512
#define B_DIM 8
#define HW (H_DIM * W_DIM)
#define NPIX (B_DIM * HW)

#define GRID_BLOCKS 896
#define CONV_BLOCKS 224
#define N_UNITS 1024            // unit = (b, 4-row strip): b*128 + (y>>2)
#define N_TILES (NPIX / 256)    // 8192 tiles of 256 px

// Packed 11/11/10 fixed-point images: 4 bytes/pixel, linear (B,H,W) layout.
__device__ __align__(16) unsigned int g_pack[2][(size_t)NPIX];
__device__ int g_flags[N_UNITS];
__device__ int g_tile_ctr;

// ---------------- init: reset flags + counter (runs every graph replay) ----
__global__ void __launch_bounds__(256)
init_kernel() {
    int i = threadIdx.x;
    #pragma unroll
    for (int k = 0; k < N_UNITS / 256; k++) g_flags[i + k * 256] = 0;
    if (i == 0) g_tile_ctr = 0;
}

// ---------------- decode helpers (unchanged from R6) ----------------
__device__ __forceinline__ float3 decode3(unsigned int q) {
    float3 f;
    f.x = __uint_as_float(((q << 12) & 0x007FF000u) | 0x3F800000u);
    f.y = __uint_as_float(((q << 1)  & 0x007FF000u) | 0x3F800000u);
    f.z = __uint_as_float(((q >> 9)  & 0x007FE000u) | 0x3F800000u);
    return f;
}

__device__ __forceinline__ float3 bilerp3q(const unsigned int* __restrict__ img,
                                           float x, float y,
                                           int x0, int x1, int y0, int y1) {
    float wx = x - floorf(x);
    float wy = y - floorf(y);
    float wa = (1.f - wx) * (1.f - wy);
    float wb = (1.f - wx) * wy;
    float wc = wx * (1.f - wy);
    float wd = wx * wy;

    const unsigned int* r0 = img + y0 * W_DIM;
    const unsigned int* r1 = img + y1 * W_DIM;
    unsigned int qa = __ldg(r0 + x0);
    unsigned int qb = __ldg(r1 + x0);
    unsigned int qc = __ldg(r0 + x1);
    unsigned int qd = __ldg(r1 + x1);

    float3 fa = decode3(qa);
    float3 fb = decode3(qb);
    float3 fc = decode3(qc);
    float3 fd = decode3(qd);

    float3 S;
    S.x = fa.x * wa + fb.x * wb + fc.x * wc + fd.x * wd;
    S.y = fa.y * wa + fb.y * wb + fc.y * wc + fd.y * wd;
    S.z = fa.z * wa + fb.z * wb + fc.z * wc + fd.z * wd;
    return S;
}

#define CLAMPI(v, hi) min(max((v), 0), (hi))

// ---------------- fused producer/consumer kernel ----------------
__global__ void __launch_bounds__(256, 6)
fused_kernel(const float* __restrict__ t,
             const float* __restrict__ I0,
             const float* __restrict__ I1,
             const float* __restrict__ interp,
             const float* __restrict__ F0,
             const float* __restrict__ F1,
             float* __restrict__ out) {
    int tid = threadIdx.x;
    int bid = blockIdx.x;

    // ======== producer phase (blocks 0..CONV_BLOCKS-1) ========
    if (bid < CONV_BLOCKS) {
        for (int u = bid; u < N_UNITS; u += CONV_BLOCKS) {
            size_t gbase = (size_t)u * 512;       // 4-px groups; 512 groups/unit
            #pragma unroll
            for (int img = 0; img < 2; img++) {
                const float* src = img ? I1 : I0;
                unsigned int* dst = &g_pack[img][0];
                #pragma unroll
                for (int k = 0; k < 2; k++) {
                    size_t g = gbase + tid + k * 256;
                    const float4* s4 = (const float4*)src + g * 3;
                    float4 A  = __ldg(s4 + 0);
                    float4 Bv = __ldg(s4 + 1);
                    float4 C  = __ldg(s4 + 2);
                    #define PACK(r, g_, b_) \
                        ( __float2uint_rn(__saturatef(r) * 2047.0f) \
                        | (__float2uint_rn(__saturatef(g_) * 2047.0f) << 11) \
                        | (__float2uint_rn(__saturatef(b_) * 1023.0f) << 22) )
                    uint4 o;
                    o.x = PACK(A.x, A.y, A.z);
                    o.y = PACK(A.w, Bv.x, Bv.y);
                    o.z = PACK(Bv.z, Bv.w, C.x);
                    o.w = PACK(C.y, C.z, C.w);
                    #undef PACK
                    ((uint4*)dst)[g] = o;
                }
            }
            __threadfence();
            __syncthreads();
            if (tid == 0) *(volatile int*)&g_flags[u] = 1;
        }
    }

    // ======== consumer phase (all blocks; converters join when done) ========
    __shared__ int s_tile;
    for (;;) {
        __syncthreads();
        if (tid == 0) s_tile = atomicAdd(&g_tile_ctr, 1);
        __syncthreads();
        int tile = s_tile;
        if (tile >= N_TILES) return;

        int idx = tile * 256 + tid;
        int b = idx >> 18;
        int p = idx & (HW - 1);
        int yi = p >> 9;
        int xi = p & (W_DIM - 1);

        // ---- streaming loads ----
        const float* ip = interp + (size_t)idx * 5;
        float c0 = __ldg(ip + 0);
        float c1 = __ldg(ip + 1);
        float c2 = __ldg(ip + 2);
        float c3 = __ldg(ip + 3);
        float c4 = __ldg(ip + 4);
        float2 f0 = __ldg((const float2*)F0 + idx);
        float2 f1 = __ldg((const float2*)F1 + idx);
        float tb = __ldg(t + b);

        float xa = (float)xi + c0 + f0.x;
        float ya = (float)yi + c1 + f0.y;
        float xb = (float)xi + c2 + f1.x;
        float yb = (float)yi + c3 + f1.y;

        int x0a = CLAMPI((int)floorf(xa), W_DIM - 1);
        int x1a = CLAMPI((int)floorf(xa) + 1, W_DIM - 1);
        int y0a = CLAMPI((int)floorf(ya), H_DIM - 1);
        int y1a = CLAMPI((int)floorf(ya) + 1, H_DIM - 1);
        int x0b = CLAMPI((int)floorf(xb), W_DIM - 1);
        int x1b = CLAMPI((int)floorf(xb) + 1, W_DIM - 1);
        int y0b = CLAMPI((int)floorf(yb), H_DIM - 1);
        int y1b = CLAMPI((int)floorf(yb) + 1, H_DIM - 1);

        // ---- wait for the strips this lane needs ----
        int ub = b << 7;
        int ua0 = ub + (y0a >> 2), ua1 = ub + (y1a >> 2);
        int ub0 = ub + (y0b >> 2), ub1 = ub + (y1b >> 2);
        int ok;
        do {
            ok = *(volatile int*)&g_flags[ua0]
               & *(volatile int*)&g_flags[ua1]
               & *(volatile int*)&g_flags[ub0]
               & *(volatile int*)&g_flags[ub1];
        } while (!__all_sync(0xFFFFFFFFu, ok));
        __threadfence();

        // ---- weights ----
        float vt0 = 1.f / (1.f + __expf(-c4));
        float vt1 = 1.f - vt0;
        float w0 = (1.f - tb) * vt0;
        float w1 = tb * vt1;
        float Cw = w0 + w1;
        float inv_den = __fdividef(1.f, Cw + 1e-12f);

        // ---- taps ----
        const unsigned int* img0 = &g_pack[0][(size_t)b * HW];
        const unsigned int* img1 = &g_pack[1][(size_t)b * HW];
        float3 S0 = bilerp3q(img0, xa, ya, x0a, x1a, y0a, y1a);
        float3 S1 = bilerp3q(img1, xb, yb, x0b, x1b, y0b, y1b);

        float mRG = (2048.0f / 2047.0f) * inv_den;
        float mB  = (1024.0f / 1023.0f) * inv_den;

        float* o = out + (size_t)idx * 3;
        o[0] = (w0 * S0.x + w1 * S1.x - Cw) * mRG;
        o[1] = (w0 * S0.y + w1 * S1.y - Cw) * mRG;
        o[2] = (w0 * S0.z + w1 * S1.z - Cw) * mB;
    }
}

extern "C" void kernel_launch(void* const* d_in, const int* in_sizes, int n_in,
                              void* d_out, int out_size) {
    const float* t      = (const float*)d_in[0];
    const float* I0     = (const float*)d_in[1];
    const float* I1     = (const float*)d_in[2];
    const float* interp = (const float*)d_in[3];
    const float* F0     = (const float*)d_in[4];
    const float* F1     = (const float*)d_in[5];
    float* out = (float*)d_out;

    init_kernel<<<1, 256>>>();
    fused_kernel<<<GRID_BLOCKS, 256>>>(t, I0, I1, interp, F0, F1, out);
}

// round 9
// speedup vs baseline: 2.3978x; 2.3978x over previous
#include <cuda_runtime.h>
#include <cstdint>

// Problem: B=8, H=512, W=512
// Inputs: t(8,1,1,1) I0,I1(8,512,512,3) interp(8,512,512,5) Fhat_t0/t1(8,512,512,2)
// Output: It (8,512,512,3) float32

#define W_DIM 512
#define H_DIM 512
#define B_DIM 8
#define HW (H_DIM * W_DIM)
#define NPIX (B_DIM * HW)

// Packed 11/11/10 fixed-point images: 4 bytes/pixel, linear (B,H,W) layout.
__device__ __align__(16) unsigned int g_pack[2][(size_t)NPIX];

__device__ __forceinline__ uint32_t smem_u32(const void* p) {
    uint32_t a;
    asm("{ .reg .u64 tmp; cvta.to.shared.u64 tmp, %1; cvt.u32.u64 %0, tmp; }"
        : "=r"(a) : "l"(p));
    return a;
}

// ---------------- pre-pass: fp32 RGB -> packed u32 (R6 version) ----------------
__global__ void __launch_bounds__(256)
convert_kernel(const float* __restrict__ I0, const float* __restrict__ I1) {
    int img = blockIdx.y;
    const float* src = img ? I1 : I0;
    int tid = blockIdx.x * blockDim.x + threadIdx.x;   // one thread = 4 pixels
    if (tid >= NPIX / 4) return;

    const float4* s4 = (const float4*)src + (size_t)tid * 3;
    float4 A  = __ldg(s4 + 0);
    float4 Bv = __ldg(s4 + 1);
    float4 C  = __ldg(s4 + 2);

    #define PACK(r, g_, b_) \
        ( __float2uint_rn(__saturatef(r) * 2047.0f) \
        | (__float2uint_rn(__saturatef(g_) * 2047.0f) << 11) \
        | (__float2uint_rn(__saturatef(b_) * 1023.0f) << 22) )
    uint4 o;
    o.x = PACK(A.x, A.y, A.z);
    o.y = PACK(A.w, Bv.x, Bv.y);
    o.z = PACK(Bv.z, Bv.w, C.x);
    o.w = PACK(C.y, C.z, C.w);
    #undef PACK

    ((uint4*)(&g_pack[img][0]))[tid] = o;
}

// ---------------- decode helpers ----------------
__device__ __forceinline__ float3 decode3(unsigned int q) {
    float3 f;
    f.x = __uint_as_float(((q << 12) & 0x007FF000u) | 0x3F800000u);
    f.y = __uint_as_float(((q << 1)  & 0x007FF000u) | 0x3F800000u);
    f.z = __uint_as_float(((q >> 9)  & 0x007FE000u) | 0x3F800000u);
    return f;
}

__device__ __forceinline__ float3 bilerp3q(const unsigned int* __restrict__ img,
                                           float x, float y) {
    float x0f = floorf(x);
    float y0f = floorf(y);
    float wx = x - x0f;
    float wy = y - y0f;
    int x0 = min(max((int)x0f, 0), W_DIM - 1);
    int x1 = min(max((int)x0f + 1, 0), W_DIM - 1);
    int y0 = min(max((int)y0f, 0), H_DIM - 1);
    int y1 = min(max((int)y0f + 1, 0), H_DIM - 1);

    float wa = (1.f - wx) * (1.f - wy);
    float wb = (1.f - wx) * wy;
    float wc = wx * (1.f - wy);
    float wd = wx * wy;

    const unsigned int* r0 = img + y0 * W_DIM;
    const unsigned int* r1 = img + y1 * W_DIM;
    unsigned int qa = __ldg(r0 + x0);
    unsigned int qb = __ldg(r1 + x0);
    unsigned int qc = __ldg(r0 + x1);
    unsigned int qd = __ldg(r1 + x1);

    float3 fa = decode3(qa);
    float3 fb = decode3(qb);
    float3 fc = decode3(qc);
    float3 fd = decode3(qd);

    float3 S;
    S.x = fa.x * wa + fb.x * wb + fc.x * wc + fd.x * wd;
    S.y = fa.y * wa + fb.y * wb + fc.y * wc + fd.y * wd;
    S.z = fa.z * wa + fb.z * wb + fc.z * wc + fd.z * wd;
    return S;
}

// ---------------- main kernel: TMA-staged streaming ----------------
__global__ void __launch_bounds__(256)
imagecomp_kernel(const float* __restrict__ t,
                 const float* __restrict__ interp,
                 const float* __restrict__ F0,
                 const float* __restrict__ F1,
                 float* __restrict__ out) {
    __shared__ __align__(16) float  s_ip[1280];    // 5120B: 256 px * 5
    __shared__ __align__(16) float2 s_f0[256];     // 2048B
    __shared__ __align__(16) float2 s_f1[256];     // 2048B
    __shared__ __align__(16) float  s_out[768];    // 3072B
    __shared__ __align__(8)  unsigned long long s_mbar;

    int tid = threadIdx.x;
    size_t base = (size_t)blockIdx.x * 256;
    uint32_t mbar = smem_u32(&s_mbar);

    if (tid == 0) {
        asm volatile("mbarrier.init.shared.b64 [%0], %1;" :: "r"(mbar), "r"(1) : "memory");
    }
    __syncthreads();

    if (tid == 0) {
        asm volatile("mbarrier.arrive.expect_tx.shared.b64 _, [%0], %1;"
                     :: "r"(mbar), "r"(9216u) : "memory");
        asm volatile("cp.async.bulk.shared::cta.global.mbarrier::complete_tx::bytes [%0], [%1], %2, [%3];"
                     :: "r"(smem_u32(s_ip)), "l"(interp + base * 5), "r"(5120u), "r"(mbar) : "memory");
        asm volatile("cp.async.bulk.shared::cta.global.mbarrier::complete_tx::bytes [%0], [%1], %2, [%3];"
                     :: "r"(smem_u32(s_f0)), "l"(F0 + base * 2), "r"(2048u), "r"(mbar) : "memory");
        asm volatile("cp.async.bulk.shared::cta.global.mbarrier::complete_tx::bytes [%0], [%1], %2, [%3];"
                     :: "r"(smem_u32(s_f1)), "l"(F1 + base * 2), "r"(2048u), "r"(mbar) : "memory");
    }

    int idx = (int)base + tid;
    int b = idx >> 18;
    int p = idx & (HW - 1);
    int yi = p >> 9;
    int xi = p & (W_DIM - 1);
    float tb = __ldg(t + b);   // independent of TMA data

    // wait for TMA completion (acquire: generic LDS follows)
    {
        uint32_t done;
        asm volatile(
            "{\n\t.reg .pred pp;\n\t"
            "mbarrier.try_wait.parity.acquire.cta.shared::cta.b64 pp, [%1], %2;\n\t"
            "selp.b32 %0, 1, 0, pp;\n\t}"
            : "=r"(done) : "r"(mbar), "r"(0u) : "memory");
        if (!done) {
            asm volatile(
                "{\n\t.reg .pred P1;\n\t"
                "WL_%=:\n\t"
                "mbarrier.try_wait.parity.acquire.cta.shared::cta.b64 P1, [%0], %1, 0x989680;\n\t"
                "@P1 bra.uni WD_%=;\n\t"
                "bra.uni WL_%=;\n\t"
                "WD_%=:\n\t}"
                :: "r"(mbar), "r"(0u) : "memory");
        }
    }

    // ---- streaming values from smem (conflict-free: strides 5 and 2x8B) ----
    float c0 = s_ip[tid * 5 + 0];
    float c1 = s_ip[tid * 5 + 1];
    float c2 = s_ip[tid * 5 + 2];
    float c3 = s_ip[tid * 5 + 3];
    float c4 = s_ip[tid * 5 + 4];
    float2 f0 = s_f0[tid];
    float2 f1 = s_f1[tid];

    float ft0x = c0 + f0.x, ft0y = c1 + f0.y;
    float ft1x = c2 + f1.x, ft1y = c3 + f1.y;

    float vt0 = 1.f / (1.f + __expf(-c4));
    float vt1 = 1.f - vt0;
    float w0 = (1.f - tb) * vt0;
    float w1 = tb * vt1;
    float Cw = w0 + w1;
    float inv_den = __fdividef(1.f, Cw + 1e-12f);

    const unsigned int* img0 = &g_pack[0][(size_t)b * HW];
    const unsigned int* img1 = &g_pack[1][(size_t)b * HW];

    float gx = (float)xi, gy = (float)yi;
    float3 S0 = bilerp3q(img0, gx + ft0x, gy + ft0y);
    float3 S1 = bilerp3q(img1, gx + ft1x, gy + ft1y);

    float mRG = (2048.0f / 2047.0f) * inv_den;
    float mB  = (1024.0f / 1023.0f) * inv_den;

    // stride-3 STS: conflict-free
    s_out[tid * 3 + 0] = (w0 * S0.x + w1 * S1.x - Cw) * mRG;
    s_out[tid * 3 + 1] = (w0 * S0.y + w1 * S1.y - Cw) * mRG;
    s_out[tid * 3 + 2] = (w0 * S0.z + w1 * S1.z - Cw) * mB;
    __syncthreads();

    if (tid == 0) {
        asm volatile("fence.proxy.async.shared::cta;" ::: "memory");
        asm volatile("cp.async.bulk.global.shared::cta.bulk_group [%0], [%1], %2;"
                     :: "l"(out + base * 3), "r"(smem_u32(s_out)), "r"(3072u) : "memory");
        asm volatile("cp.async.bulk.commit_group;" ::: "memory");
        asm volatile("cp.async.bulk.wait_group 0;" ::: "memory");
    }
}

extern "C" void kernel_launch(void* const* d_in, const int* in_sizes, int n_in,
                              void* d_out, int out_size) {
    const float* t      = (const float*)d_in[0];
    const float* I0     = (const float*)d_in[1];
    const float* I1     = (const float*)d_in[2];
    const float* interp = (const float*)d_in[3];
    const float* F0     = (const float*)d_in[4];
    const float* F1     = (const float*)d_in[5];
    float* out = (float*)d_out;

    dim3 cgrid((NPIX / 4 + 255) / 256, 2);   // 2048 x 2
    convert_kernel<<<cgrid, 256>>>(I0, I1);

    imagecomp_kernel<<<NPIX / 256, 256>>>(t, interp, F0, F1, out);
}